// round 4
// baseline (speedup 1.0000x reference)
#include <cuda_runtime.h>
#include <cstdint>

#define BATCH  512
#define SEQ    41
#define DMODEL 64
#define NLAYER 3
#define DINNER 128
#define NSTATE 16
#define DTRANK 4
#define KCONV  4
#define NSTACK 3
#define TOK    (BATCH*SEQ)          /* 20992 tokens per stack  */
#define TOKALL (NSTACK*TOK)         /* 62976                   */
#define NH1    384
#define NH2    16
#define FLAT   (SEQ*DMODEL)         /* 2624                    */
#define KSPLIT 4
#define KCHUNK (FLAT/KSPLIT)        /* 656, multiple of 16     */

// ---------------- scratch (static device globals; no allocation) ----------------
__device__ __align__(16) float g_x    [(size_t)TOKALL*DMODEL];     // residual stream per stack
__device__ __align__(16) float g_xin  [(size_t)TOKALL*DMODEL];     // rmsnorm output
__device__ __align__(16) float g_ures [(size_t)TOKALL*2*DINNER];   // [u | res] from in_proj
__device__ __align__(16) float g_dbl  [(size_t)TOKALL*36];         // x_proj output (dt_in|B|C)
__device__ __align__(16) float g_ys   [(size_t)TOKALL*DINNER];     // y * silu(res)
__device__ __align__(16) float g_fused[(size_t)BATCH*FLAT];        // fused flat features
__device__ __align__(16) float g_h1p  [(size_t)KSPLIT*BATCH*NH1];  // split-K partials (deterministic)
__device__ __align__(16) float g_h1   [(size_t)BATCH*NH1];         // relu(h1)

// buffer tags for the templated GEMM (device-side symbol resolution; keeps
// kernel_launch free of any runtime API besides kernel launches)
#define BUF_XIN   0
#define BUF_URES  1
#define BUF_DBL   2
#define BUF_YS    3
#define BUF_X     4
#define BUF_FUSED 5
#define BUF_H1P   6

template<int WHICH> __device__ __forceinline__ float* buf_ptr();
template<> __device__ __forceinline__ float* buf_ptr<BUF_XIN>()   { return g_xin;   }
template<> __device__ __forceinline__ float* buf_ptr<BUF_URES>()  { return g_ures;  }
template<> __device__ __forceinline__ float* buf_ptr<BUF_DBL>()   { return g_dbl;   }
template<> __device__ __forceinline__ float* buf_ptr<BUF_YS>()    { return g_ys;    }
template<> __device__ __forceinline__ float* buf_ptr<BUF_X>()     { return g_x;     }
template<> __device__ __forceinline__ float* buf_ptr<BUF_FUSED>() { return g_fused; }
template<> __device__ __forceinline__ float* buf_ptr<BUF_H1P>()   { return g_h1p;   }

// ---------------- embedding ----------------
__global__ void k_embed(const int* __restrict__ ids, const float* __restrict__ emb) {
    int idx = blockIdx.x * blockDim.x + threadIdx.x;
    if (idx >= TOKALL * DMODEL) return;
    int d   = idx & (DMODEL - 1);
    int tok = (idx >> 6) % TOK;
    g_x[idx] = emb[(size_t)ids[tok] * DMODEL + d];
}

// ---------------- rmsnorm (warp per token) ----------------
__global__ void k_rms(const float* __restrict__ norm_w, int layer) {
    int gw   = (blockIdx.x * blockDim.x + threadIdx.x) >> 5;   // global warp == token id (stacked)
    int lane = threadIdx.x & 31;
    if (gw >= TOKALL) return;
    int s = gw / TOK;
    size_t base = (size_t)gw * DMODEL;
    float x1 = g_x[base + lane];
    float x2 = g_x[base + 32 + lane];
    float ss = x1 * x1 + x2 * x2;
    #pragma unroll
    for (int o = 16; o; o >>= 1) ss += __shfl_xor_sync(0xffffffffu, ss, o);
    float rn = rsqrtf(ss * (1.0f / DMODEL) + 1e-5f);
    const float* nw = norm_w + (size_t)(s * NLAYER + layer) * DMODEL;
    g_xin[base + lane]      = x1 * rn * nw[lane];
    g_xin[base + 32 + lane] = x2 * rn * nw[32 + lane];
}

// ---------------- generic tiled GEMM: C[M,N] (+)= A[M,K] * B[K,N] ----------------
// 256 threads, 64x64 tile, 4x4 register tile, BK=16. blockIdx.z selects either a
// stack (via strides) or a K-split chunk (via kOffPerZ). EPI: 0=store, 1=add.
// A and C are static scratch buffers chosen by template tag; B is a weight
// pointer passed from the harness inputs.
template<int ABUF, int CBUF, int EPI>
__global__ __launch_bounds__(256) void k_gemm(
    const float* __restrict__ Bw,
    int N, int kLen, int lda, int ldb, int ldc,
    long long sAz, long long sBz, long long sCz, int kOffPerZ)
{
    int z = blockIdx.z;
    const float* A = buf_ptr<ABUF>() + (size_t)z * sAz + (size_t)z * kOffPerZ;
    float*       C = buf_ptr<CBUF>() + (size_t)z * sCz;
    Bw += (size_t)z * sBz + (size_t)z * kOffPerZ * ldb;

    const int m0 = blockIdx.x * 64;
    const int n0 = blockIdx.y * 64;

    __shared__ float As[16][68];   // transposed: As[k][m]
    __shared__ float Bs[16][68];   // Bs[k][n]

    int tid = threadIdx.x;
    int tx = tid & 15, ty = tid >> 4;
    int am = tid >> 2;                  // 0..63
    int ak = (tid & 3) * 4;             // 0,4,8,12
    int bn = tid & 63;                  // 0..63
    int bk = tid >> 6;                  // 0..3

    float acc[4][4] = {};

    for (int k0 = 0; k0 < kLen; k0 += 16) {
        float4 va = *reinterpret_cast<const float4*>(&A[(size_t)(m0 + am) * lda + k0 + ak]);
        As[ak + 0][am] = va.x; As[ak + 1][am] = va.y;
        As[ak + 2][am] = va.z; As[ak + 3][am] = va.w;
        #pragma unroll
        for (int kk = 0; kk < 4; kk++) {
            int krow = bk + kk * 4;
            int n = n0 + bn;
            Bs[krow][bn] = (n < N) ? Bw[(size_t)(k0 + krow) * ldb + n] : 0.0f;
        }
        __syncthreads();
        #pragma unroll
        for (int k = 0; k < 16; k++) {
            float4 a4 = *reinterpret_cast<const float4*>(&As[k][ty * 4]);
            float4 b4 = *reinterpret_cast<const float4*>(&Bs[k][tx * 4]);
            float av[4] = {a4.x, a4.y, a4.z, a4.w};
            float bv[4] = {b4.x, b4.y, b4.z, b4.w};
            #pragma unroll
            for (int i = 0; i < 4; i++)
                #pragma unroll
                for (int j = 0; j < 4; j++)
                    acc[i][j] = fmaf(av[i], bv[j], acc[i][j]);
        }
        __syncthreads();
    }

    #pragma unroll
    for (int i = 0; i < 4; i++) {
        int m = m0 + ty * 4 + i;
        #pragma unroll
        for (int j = 0; j < 4; j++) {
            int n = n0 + tx * 4 + j;
            if (n < N) {
                size_t off = (size_t)m * ldc + n;
                if (EPI == 0) C[off] = acc[i][j];
                else          C[off] += acc[i][j];
            }
        }
    }
}

// ---------------- depthwise causal conv + SiLU, in place on u part of g_ures ----------------
__global__ void k_conv(const float* __restrict__ cw, const float* __restrict__ cb, int layer) {
    int idx = blockIdx.x * blockDim.x + threadIdx.x;
    if (idx >= NSTACK * BATCH * DINNER) return;
    int c = idx % DINNER;
    int b = (idx / DINNER) % BATCH;
    int s = idx / (DINNER * BATCH);
    int wo = (s * NLAYER + layer) * DINNER + c;
    float w0 = cw[(size_t)wo * KCONV + 0];
    float w1 = cw[(size_t)wo * KCONV + 1];
    float w2 = cw[(size_t)wo * KCONV + 2];
    float w3 = cw[(size_t)wo * KCONV + 3];
    float bias = cb[wo];
    size_t base = ((size_t)(s * TOK + b * SEQ)) * (2 * DINNER) + c;
    float p0 = 0.f, p1 = 0.f, p2 = 0.f;
    for (int t = 0; t < SEQ; t++) {
        float cur = g_ures[base + (size_t)t * (2 * DINNER)];
        float v = fmaf(w0, p0, fmaf(w1, p1, fmaf(w2, p2, fmaf(w3, cur, bias))));
        v = v / (1.0f + __expf(-v));             // silu
        g_ures[base + (size_t)t * (2 * DINNER)] = v;
        p0 = p1; p1 = p2; p2 = cur;
    }
}

// ---------------- dt (softplus) + selective scan + *silu(res); CTA per (stack,batch) ----------------
__global__ __launch_bounds__(DINNER) void k_scan(
    const float* __restrict__ dt_w, const float* __restrict__ dt_b,
    const float* __restrict__ A_log, const float* __restrict__ Dp, int layer)
{
    __shared__ float sd[SEQ * 36];
    int bx = blockIdx.x;
    int s = bx / BATCH, b = bx % BATCH;
    int d = threadIdx.x;

    const float* dsrc = g_dbl + (size_t)(s * TOK + b * SEQ) * 36;
    for (int i = d; i < SEQ * 36; i += DINNER) sd[i] = dsrc[i];

    int wo = s * NLAYER + layer;
    float aL[NSTATE];
    #pragma unroll
    for (int n = 0; n < NSTATE; n++)
        aL[n] = -__expf(A_log[((size_t)wo * DINNER + d) * NSTATE + n]);
    float w0 = dt_w[((size_t)wo * DTRANK + 0) * DINNER + d];
    float w1 = dt_w[((size_t)wo * DTRANK + 1) * DINNER + d];
    float w2 = dt_w[((size_t)wo * DTRANK + 2) * DINNER + d];
    float w3 = dt_w[((size_t)wo * DTRANK + 3) * DINNER + d];
    float bdt = dt_b[(size_t)wo * DINNER + d];
    float dpv = Dp[(size_t)wo * DINNER + d];
    __syncthreads();

    float h[NSTATE];
    #pragma unroll
    for (int n = 0; n < NSTATE; n++) h[n] = 0.f;

    size_t ub = (size_t)(s * TOK + b * SEQ) * (2 * DINNER) + d;
    size_t yb = (size_t)(s * TOK + b * SEQ) * DINNER + d;

    for (int t = 0; t < SEQ; t++) {
        const float* row = sd + t * 36;
        float xdt = fmaf(row[0], w0, fmaf(row[1], w1, fmaf(row[2], w2, fmaf(row[3], w3, bdt))));
        float dt = (xdt > 20.f) ? xdt : log1pf(__expf(xdt));  // softplus
        float u  = g_ures[ub + (size_t)t * (2 * DINNER)];
        float du = dt * u;
        float y = 0.f;
        #pragma unroll
        for (int n = 0; n < NSTATE; n++) {
            float dA = __expf(dt * aL[n]);
            h[n] = fmaf(dA, h[n], du * row[4 + n]);
            y = fmaf(h[n], row[20 + n], y);
        }
        y = fmaf(u, dpv, y);
        float r = g_ures[ub + (size_t)t * (2 * DINNER) + DINNER];
        float sr = r / (1.0f + __expf(-r));       // silu(res)
        g_ys[yb + (size_t)t * DINNER] = y * sr;
    }
}

// ---------------- final rmsnorm + softmax-weighted fusion (warp per (b,t)) ----------------
__global__ void k_fuse(const float* __restrict__ nfw, const float* __restrict__ fw) {
    int gw   = (blockIdx.x * blockDim.x + threadIdx.x) >> 5;   // token (b*SEQ + t)
    int lane = threadIdx.x & 31;
    if (gw >= TOK) return;
    float e0 = __expf(fw[0]), e1 = __expf(fw[1]), e2 = __expf(fw[2]);
    float inv = 1.0f / (e0 + e1 + e2);
    float ws[3] = {e0 * inv, e1 * inv, e2 * inv};
    float n1 = nfw[lane], n2 = nfw[32 + lane];
    float acc1 = 0.f, acc2 = 0.f;
    for (int s = 0; s < NSTACK; s++) {
        size_t base = ((size_t)(s * TOK) + gw) * DMODEL;
        float x1 = g_x[base + lane];
        float x2 = g_x[base + 32 + lane];
        float ss = x1 * x1 + x2 * x2;
        #pragma unroll
        for (int o = 16; o; o >>= 1) ss += __shfl_xor_sync(0xffffffffu, ss, o);
        float rn = rsqrtf(ss * (1.0f / DMODEL) + 1e-5f);
        acc1 = fmaf(ws[s], x1 * rn * n1, acc1);
        acc2 = fmaf(ws[s], x2 * rn * n2, acc2);
    }
    g_fused[(size_t)gw * DMODEL + lane]      = acc1;   // row b, offset t*64 + d
    g_fused[(size_t)gw * DMODEL + 32 + lane] = acc2;
}

// ---------------- reduce split-K partials + bias + relu ----------------
__global__ void k_brelu(const float* __restrict__ b1) {
    int idx = blockIdx.x * blockDim.x + threadIdx.x;
    if (idx >= BATCH * NH1) return;
    int n = idx % NH1;
    float v = b1[n];
    #pragma unroll
    for (int z = 0; z < KSPLIT; z++) v += g_h1p[(size_t)z * BATCH * NH1 + idx];
    g_h1[idx] = fmaxf(v, 0.f);
}

// ---------------- MLP tail: h1 @ W2 -> relu -> @ W3 -> sigmoid ----------------
__global__ void k_tail(const float* __restrict__ W2, const float* __restrict__ b2,
                       const float* __restrict__ W3, const float* __restrict__ b3,
                       float* __restrict__ out)
{
    int b = blockIdx.x * blockDim.x + threadIdx.x;
    if (b >= BATCH) return;
    const float* h = g_h1 + (size_t)b * NH1;
    float acc[NH2];
    #pragma unroll
    for (int j = 0; j < NH2; j++) acc[j] = b2[j];
    for (int k = 0; k < NH1; k++) {
        float hk = h[k];
        #pragma unroll
        for (int j = 0; j < NH2; j++)
            acc[j] = fmaf(hk, W2[(size_t)k * NH2 + j], acc[j]);
    }
    float logit = b3[0];
    #pragma unroll
    for (int j = 0; j < NH2; j++)
        logit = fmaf(fmaxf(acc[j], 0.f), W3[j], logit);
    out[b] = 1.0f / (1.0f + __expf(-logit));
}

// ---------------- launch (pure kernel launches; no runtime API calls) ----------------
extern "C" void kernel_launch(void* const* d_in, const int* in_sizes, int n_in,
                              void* d_out, int out_size)
{
    const int*   ids = (const int*)  d_in[0];
    const float* emb = (const float*)d_in[1];
    const float* ip  = (const float*)d_in[2];
    const float* cw  = (const float*)d_in[3];
    const float* cb  = (const float*)d_in[4];
    const float* xp  = (const float*)d_in[5];
    const float* dw  = (const float*)d_in[6];
    const float* db  = (const float*)d_in[7];
    const float* al  = (const float*)d_in[8];
    const float* dp  = (const float*)d_in[9];
    const float* op  = (const float*)d_in[10];
    const float* nw  = (const float*)d_in[11];
    const float* nfw = (const float*)d_in[12];
    const float* fw  = (const float*)d_in[13];
    const float* W1  = (const float*)d_in[14];
    const float* b1  = (const float*)d_in[15];
    const float* W2  = (const float*)d_in[16];
    const float* b2  = (const float*)d_in[17];
    const float* W3  = (const float*)d_in[18];
    const float* b3  = (const float*)d_in[19];
    float* out = (float*)d_out;

    k_embed<<<(TOKALL * DMODEL + 255) / 256, 256>>>(ids, emb);

    for (int layer = 0; layer < NLAYER; layer++) {
        k_rms<<<(TOKALL * 32) / 256, 256>>>(nw, layer);

        // in_proj: [TOK,64] @ [64,256] -> g_ures, per stack
        k_gemm<BUF_XIN, BUF_URES, 0><<<dim3(TOK / 64, 4, NSTACK), 256>>>(
            ip + (size_t)layer * DMODEL * 2 * DINNER,
            2 * DINNER, DMODEL, DMODEL, 2 * DINNER, 2 * DINNER,
            (long long)TOK * DMODEL, (long long)NLAYER * DMODEL * 2 * DINNER,
            (long long)TOK * 2 * DINNER, 0);

        k_conv<<<(NSTACK * BATCH * DINNER) / 256, 256>>>(cw, cb, layer);

        // x_proj: [TOK,128] (u part, lda=256) @ [128,36] -> g_dbl
        k_gemm<BUF_URES, BUF_DBL, 0><<<dim3(TOK / 64, 1, NSTACK), 256>>>(
            xp + (size_t)layer * DINNER * 36,
            36, DINNER, 2 * DINNER, 36, 36,
            (long long)TOK * 2 * DINNER, (long long)NLAYER * DINNER * 36,
            (long long)TOK * 36, 0);

        k_scan<<<NSTACK * BATCH, DINNER>>>(dw, db, al, dp, layer);

        // out_proj: [TOK,128] @ [128,64] -> residual add into g_x
        k_gemm<BUF_YS, BUF_X, 1><<<dim3(TOK / 64, 1, NSTACK), 256>>>(
            op + (size_t)layer * DINNER * DMODEL,
            DMODEL, DINNER, DINNER, DMODEL, DMODEL,
            (long long)TOK * DINNER, (long long)NLAYER * DINNER * DMODEL,
            (long long)TOK * DMODEL, 0);
    }

    k_fuse<<<(TOK * 32) / 256, 256>>>(nfw, fw);

    // MLP1: [512,2624] @ [2624,384], split-K=4 into deterministic partials
    k_gemm<BUF_FUSED, BUF_H1P, 0><<<dim3(BATCH / 64, NH1 / 64, KSPLIT), 256>>>(
        W1,
        NH1, KCHUNK, FLAT, NH1, NH1,
        0, 0, (long long)BATCH * NH1, KCHUNK);

    k_brelu<<<(BATCH * NH1) / 256, 256>>>(b1);
    k_tail<<<2, 256>>>(W2, b2, W3, b3, out);
}

// round 5
// speedup vs baseline: 1.1076x; 1.1076x over previous
#include <cuda_runtime.h>
#include <cstdint>

#define BATCH  512
#define SEQ    41
#define DMODEL 64
#define NLAYER 3
#define DINNER 128
#define NSTATE 16
#define DTRANK 4
#define KCONV  4
#define NSTACK 3
#define TOK    (BATCH*SEQ)          /* 20992 tokens per stack  */
#define TOKALL (NSTACK*TOK)         /* 62976                   */
#define NH1    384
#define NH2    16
#define FLAT   (SEQ*DMODEL)         /* 2624                    */
#define KSPLIT 4
#define KCHUNK (FLAT/KSPLIT)        /* 656, multiple of 16     */

// ---------------- scratch (static device globals; no allocation) ----------------
__device__ __align__(16) float g_x    [(size_t)TOKALL*DMODEL];     // residual stream per stack
__device__ __align__(16) float g_ures [(size_t)TOKALL*2*DINNER];   // [u | res] from in_proj
__device__ __align__(16) float g_ys   [(size_t)TOKALL*DINNER];     // y * silu(res)
__device__ __align__(16) float g_fused[(size_t)BATCH*FLAT];        // fused flat features
__device__ __align__(16) float g_h1p  [(size_t)KSPLIT*BATCH*NH1];  // split-K partials
__device__ __align__(16) float g_h1   [(size_t)BATCH*NH1];         // relu(h1)

// buffer tags for the generic GEMM
#define BUF_YS    0
#define BUF_X     1
#define BUF_FUSED 2
#define BUF_H1P   3
template<int WHICH> __device__ __forceinline__ float* buf_ptr();
template<> __device__ __forceinline__ float* buf_ptr<BUF_YS>()    { return g_ys;    }
template<> __device__ __forceinline__ float* buf_ptr<BUF_X>()     { return g_x;     }
template<> __device__ __forceinline__ float* buf_ptr<BUF_FUSED>() { return g_fused; }
template<> __device__ __forceinline__ float* buf_ptr<BUF_H1P>()   { return g_h1p;   }

// ---------------- embedding ----------------
__global__ void k_embed(const int* __restrict__ ids, const float* __restrict__ emb) {
    int idx = blockIdx.x * blockDim.x + threadIdx.x;
    if (idx >= TOKALL * DMODEL) return;
    int d   = idx & (DMODEL - 1);
    int tok = (idx >> 6) % TOK;
    g_x[idx] = emb[(size_t)ids[tok] * DMODEL + d];
}

// ---------------- fused rmsnorm + in_proj GEMM ----------------
// C[128,128] = rms(A[128,64]) @ (nw ⊙ W)[64, n0+128]. Tile 128x128, 8x8/thread,
// full K=64 staged once in smem. rms row-scale applied in epilogue (linear).
// grid (TOK/128, 2, NSTACK)
#define IP_SMEM_FLOATS (64*132*2 + 128 + 64)
__global__ __launch_bounds__(256) void k_inproj(
    const float* __restrict__ ipw,   // + layer offset, stride NLAYER*64*256 per stack
    const float* __restrict__ nwp)   // + layer offset, stride NLAYER*64 per stack
{
    extern __shared__ float sm[];
    float* As  = sm;                 // [64][132] transposed, raw x
    float* Bs  = sm + 64*132;        // [64][132]  W * nw[k]
    float* srn = sm + 2*64*132;      // [128]
    float* snw = srn + 128;          // [64]

    int z = blockIdx.z;
    const float* A  = g_x + (size_t)z * TOK * DMODEL + (size_t)blockIdx.x * 128 * DMODEL;
    const float* Bw = ipw + (size_t)z * (NLAYER * DMODEL * 2 * DINNER);
    const float* nw = nwp + (size_t)z * (NLAYER * DMODEL);
    float* C = g_ures + (size_t)z * TOK * (2*DINNER)
             + (size_t)blockIdx.x * 128 * (2*DINNER) + (size_t)blockIdx.y * 128;

    int tid = threadIdx.x;
    if (tid < 64) snw[tid] = nw[tid];
    // load A tile (128 rows x full K=64), transposed into smem
    {
        int row = tid >> 1, kb = (tid & 1) * 32;
        const float4* ar = reinterpret_cast<const float4*>(A + row * DMODEL + kb);
        #pragma unroll
        for (int i = 0; i < 8; i++) {
            float4 v = ar[i];
            int k = kb + i * 4;
            As[(k+0)*132 + row] = v.x; As[(k+1)*132 + row] = v.y;
            As[(k+2)*132 + row] = v.z; As[(k+3)*132 + row] = v.w;
        }
    }
    __syncthreads();
    // load B tile scaled by nw[k]; compute per-row rsqrt factors
    for (int idx = tid; idx < 64 * 128; idx += 256) {
        int k = idx >> 7, n = idx & 127;
        Bs[k*132 + n] = Bw[(size_t)k * (2*DINNER) + (size_t)blockIdx.y * 128 + n] * snw[k];
    }
    if (tid < 128) {
        float ss = 0.f;
        #pragma unroll
        for (int k = 0; k < 64; k++) { float v = As[k*132 + tid]; ss = fmaf(v, v, ss); }
        srn[tid] = rsqrtf(ss * (1.0f / DMODEL) + 1e-5f);
    }
    __syncthreads();

    float acc[8][8] = {};
    int ty = tid >> 4, tx = tid & 15;
    #pragma unroll 4
    for (int k = 0; k < 64; k++) {
        float4 a0 = *reinterpret_cast<float4*>(&As[k*132 + ty*8]);
        float4 a1 = *reinterpret_cast<float4*>(&As[k*132 + ty*8 + 4]);
        float4 b0 = *reinterpret_cast<float4*>(&Bs[k*132 + tx*8]);
        float4 b1 = *reinterpret_cast<float4*>(&Bs[k*132 + tx*8 + 4]);
        float av[8] = {a0.x,a0.y,a0.z,a0.w,a1.x,a1.y,a1.z,a1.w};
        float bv[8] = {b0.x,b0.y,b0.z,b0.w,b1.x,b1.y,b1.z,b1.w};
        #pragma unroll
        for (int i = 0; i < 8; i++)
            #pragma unroll
            for (int j = 0; j < 8; j++)
                acc[i][j] = fmaf(av[i], bv[j], acc[i][j]);
    }
    #pragma unroll
    for (int i = 0; i < 8; i++) {
        float rn = srn[ty*8 + i];
        float4 o0 = make_float4(acc[i][0]*rn, acc[i][1]*rn, acc[i][2]*rn, acc[i][3]*rn);
        float4 o1 = make_float4(acc[i][4]*rn, acc[i][5]*rn, acc[i][6]*rn, acc[i][7]*rn);
        float* cp = C + (size_t)(ty*8 + i) * (2*DINNER) + tx*8;
        *reinterpret_cast<float4*>(cp)     = o0;
        *reinterpret_cast<float4*>(cp + 4) = o1;
    }
}

// ---------------- fused conv+silu + x_proj + dt/softplus + scan + silu(res) ----------------
// CTA per (stack, batch). All intermediates in smem.
#define MB_SMEM_FLOATS (41*260 + 128*36 + 41*36)
__global__ __launch_bounds__(256) void k_mamba(
    const float* __restrict__ xpw, const float* __restrict__ cw, const float* __restrict__ cb,
    const float* __restrict__ dtw, const float* __restrict__ dtb,
    const float* __restrict__ alog, const float* __restrict__ dpp, int layer)
{
    extern __shared__ float sm[];
    float* raw  = sm;                 // [41][260]: [u(128)|res(128)] per row, padded
    float* sxp  = sm + 41*260;        // [128][36]
    float* sdbl = sxp + 128*36;       // [41][36]

    int bx = blockIdx.x;
    int s = bx / BATCH, b = bx % BATCH;
    int tid = threadIdx.x;
    int wo = s * NLAYER + layer;
    size_t tok0 = (size_t)s * TOK + (size_t)b * SEQ;

    const float4* src = reinterpret_cast<const float4*>(g_ures + tok0 * (2*DINNER));
    for (int idx = tid; idx < SEQ * 64; idx += 256) {
        int t = idx >> 6, q = idx & 63;
        *reinterpret_cast<float4*>(raw + t*260 + q*4) = src[t*64 + q];
    }
    __syncthreads();

    if (tid < DINNER) {
        // depthwise causal conv (K=4) + silu, in place on u columns
        int d = tid;
        size_t co = (size_t)wo * DINNER + d;
        float w0 = cw[co*4], w1 = cw[co*4+1], w2 = cw[co*4+2], w3 = cw[co*4+3];
        float bias = cb[co];
        float p0 = 0.f, p1 = 0.f, p2 = 0.f;
        for (int t = 0; t < SEQ; t++) {
            float cur = raw[t*260 + d];
            float v = fmaf(w0, p0, fmaf(w1, p1, fmaf(w2, p2, fmaf(w3, cur, bias))));
            v = v / (1.0f + __expf(-v));
            raw[t*260 + d] = v;
            p0 = p1; p1 = p2; p2 = cur;
        }
    } else {
        const float* gx = xpw + (size_t)wo * DINNER * 36;
        for (int idx = tid - 128; idx < DINNER * 36; idx += 128) sxp[idx] = gx[idx];
    }
    __syncthreads();

    // dbl[41][36] = u_conv[41][128] @ xp[128][36]
    if (tid < 246) {
        int t = tid / 6, jg = tid % 6;
        float acc[6] = {};
        const float* ur = raw + t*260;
        for (int k = 0; k < DINNER; k++) {
            float a = ur[k];
            const float* xr = sxp + k*36 + jg*6;
            #pragma unroll
            for (int j = 0; j < 6; j++) acc[j] = fmaf(a, xr[j], acc[j]);
        }
        #pragma unroll
        for (int j = 0; j < 6; j++) sdbl[t*36 + jg*6 + j] = acc[j];
    }
    __syncthreads();

    if (tid < DINNER) {
        int d = tid;
        float aL[NSTATE];
        #pragma unroll
        for (int n = 0; n < NSTATE; n++)
            aL[n] = -__expf(alog[((size_t)wo * DINNER + d) * NSTATE + n]);
        float w0 = dtw[((size_t)wo * DTRANK + 0) * DINNER + d];
        float w1 = dtw[((size_t)wo * DTRANK + 1) * DINNER + d];
        float w2 = dtw[((size_t)wo * DTRANK + 2) * DINNER + d];
        float w3 = dtw[((size_t)wo * DTRANK + 3) * DINNER + d];
        float bdt = dtb[(size_t)wo * DINNER + d];
        float dpv = dpp[(size_t)wo * DINNER + d];
        float h[NSTATE];
        #pragma unroll
        for (int n = 0; n < NSTATE; n++) h[n] = 0.f;
        float* yout = g_ys + tok0 * DINNER + d;

        for (int t = 0; t < SEQ; t++) {
            const float* row = sdbl + t*36;
            float xdt = fmaf(row[0], w0, fmaf(row[1], w1, fmaf(row[2], w2, fmaf(row[3], w3, bdt))));
            float dt = (xdt > 20.f) ? xdt : log1pf(__expf(xdt));
            float u  = raw[t*260 + d];
            float du = dt * u;
            float y = 0.f;
            #pragma unroll
            for (int n = 0; n < NSTATE; n++) {
                float dA = __expf(dt * aL[n]);
                h[n] = fmaf(dA, h[n], du * row[4 + n]);
                y = fmaf(h[n], row[20 + n], y);
            }
            y = fmaf(u, dpv, y);
            float r = raw[t*260 + DINNER + d];
            float sr = r / (1.0f + __expf(-r));
            yout[(size_t)t * DINNER] = y * sr;
        }
    }
}

// ---------------- generic tiled GEMM: C[M,N] (+)= A[M,K] * B[K,N] ----------------
template<int ABUF, int CBUF, int EPI>
__global__ __launch_bounds__(256) void k_gemm(
    const float* __restrict__ Bw,
    int N, int kLen, int lda, int ldb, int ldc,
    long long sAz, long long sBz, long long sCz, int kOffPerZ)
{
    int z = blockIdx.z;
    const float* A = buf_ptr<ABUF>() + (size_t)z * sAz + (size_t)z * kOffPerZ;
    float*       C = buf_ptr<CBUF>() + (size_t)z * sCz;
    Bw += (size_t)z * sBz + (size_t)z * kOffPerZ * ldb;

    const int m0 = blockIdx.x * 64;
    const int n0 = blockIdx.y * 64;
    __shared__ float As[16][68];
    __shared__ float Bs[16][68];
    int tid = threadIdx.x;
    int tx = tid & 15, ty = tid >> 4;
    int am = tid >> 2, ak = (tid & 3) * 4;
    int bn = tid & 63, bk = tid >> 6;
    float acc[4][4] = {};

    for (int k0 = 0; k0 < kLen; k0 += 16) {
        float4 va = *reinterpret_cast<const float4*>(&A[(size_t)(m0 + am) * lda + k0 + ak]);
        As[ak+0][am] = va.x; As[ak+1][am] = va.y; As[ak+2][am] = va.z; As[ak+3][am] = va.w;
        #pragma unroll
        for (int kk = 0; kk < 4; kk++) {
            int krow = bk + kk * 4;
            int n = n0 + bn;
            Bs[krow][bn] = (n < N) ? Bw[(size_t)(k0 + krow) * ldb + n] : 0.0f;
        }
        __syncthreads();
        #pragma unroll
        for (int k = 0; k < 16; k++) {
            float4 a4 = *reinterpret_cast<const float4*>(&As[k][ty*4]);
            float4 b4 = *reinterpret_cast<const float4*>(&Bs[k][tx*4]);
            float av[4] = {a4.x, a4.y, a4.z, a4.w};
            float bv[4] = {b4.x, b4.y, b4.z, b4.w};
            #pragma unroll
            for (int i = 0; i < 4; i++)
                #pragma unroll
                for (int j = 0; j < 4; j++)
                    acc[i][j] = fmaf(av[i], bv[j], acc[i][j]);
        }
        __syncthreads();
    }
    #pragma unroll
    for (int i = 0; i < 4; i++) {
        int m = m0 + ty*4 + i;
        #pragma unroll
        for (int j = 0; j < 4; j++) {
            int n = n0 + tx*4 + j;
            if (n < N) {
                size_t off = (size_t)m * ldc + n;
                if (EPI == 0) C[off] = acc[i][j];
                else          C[off] += acc[i][j];
            }
        }
    }
}

// ---------------- final rmsnorm + softmax-weighted fusion (warp per (b,t)) ----------------
__global__ void k_fuse(const float* __restrict__ nfw, const float* __restrict__ fw) {
    int gw   = (blockIdx.x * blockDim.x + threadIdx.x) >> 5;
    int lane = threadIdx.x & 31;
    if (gw >= TOK) return;
    float e0 = __expf(fw[0]), e1 = __expf(fw[1]), e2 = __expf(fw[2]);
    float inv = 1.0f / (e0 + e1 + e2);
    float ws[3] = {e0 * inv, e1 * inv, e2 * inv};
    float n1 = nfw[lane], n2 = nfw[32 + lane];
    float acc1 = 0.f, acc2 = 0.f;
    for (int s = 0; s < NSTACK; s++) {
        size_t base = ((size_t)(s * TOK) + gw) * DMODEL;
        float x1 = g_x[base + lane];
        float x2 = g_x[base + 32 + lane];
        float ss = x1 * x1 + x2 * x2;
        #pragma unroll
        for (int o = 16; o; o >>= 1) ss += __shfl_xor_sync(0xffffffffu, ss, o);
        float rn = rsqrtf(ss * (1.0f / DMODEL) + 1e-5f);
        acc1 = fmaf(ws[s], x1 * rn * n1, acc1);
        acc2 = fmaf(ws[s], x2 * rn * n2, acc2);
    }
    g_fused[(size_t)gw * DMODEL + lane]      = acc1;
    g_fused[(size_t)gw * DMODEL + 32 + lane] = acc2;
}

// ---------------- reduce split-K partials + bias + relu ----------------
__global__ void k_brelu(const float* __restrict__ b1) {
    int idx = blockIdx.x * blockDim.x + threadIdx.x;
    if (idx >= BATCH * NH1) return;
    int n = idx % NH1;
    float v = b1[n];
    #pragma unroll
    for (int z = 0; z < KSPLIT; z++) v += g_h1p[(size_t)z * BATCH * NH1 + idx];
    g_h1[idx] = fmaxf(v, 0.f);
}

// ---------------- MLP tail ----------------
__global__ void k_tail(const float* __restrict__ W2, const float* __restrict__ b2,
                       const float* __restrict__ W3, const float* __restrict__ b3,
                       float* __restrict__ out)
{
    int b = blockIdx.x * blockDim.x + threadIdx.x;
    if (b >= BATCH) return;
    const float* h = g_h1 + (size_t)b * NH1;
    float acc[NH2];
    #pragma unroll
    for (int j = 0; j < NH2; j++) acc[j] = b2[j];
    for (int k = 0; k < NH1; k++) {
        float hk = h[k];
        #pragma unroll
        for (int j = 0; j < NH2; j++)
            acc[j] = fmaf(hk, W2[(size_t)k * NH2 + j], acc[j]);
    }
    float logit = b3[0];
    #pragma unroll
    for (int j = 0; j < NH2; j++)
        logit = fmaf(fmaxf(acc[j], 0.f), W3[j], logit);
    out[b] = 1.0f / (1.0f + __expf(-logit));
}

// ---------------- launch ----------------
extern "C" void kernel_launch(void* const* d_in, const int* in_sizes, int n_in,
                              void* d_out, int out_size)
{
    const int*   ids = (const int*)  d_in[0];
    const float* emb = (const float*)d_in[1];
    const float* ip  = (const float*)d_in[2];
    const float* cw  = (const float*)d_in[3];
    const float* cb  = (const float*)d_in[4];
    const float* xp  = (const float*)d_in[5];
    const float* dw  = (const float*)d_in[6];
    const float* db  = (const float*)d_in[7];
    const float* al  = (const float*)d_in[8];
    const float* dp  = (const float*)d_in[9];
    const float* op  = (const float*)d_in[10];
    const float* nw  = (const float*)d_in[11];
    const float* nfw = (const float*)d_in[12];
    const float* fw  = (const float*)d_in[13];
    const float* W1  = (const float*)d_in[14];
    const float* b1  = (const float*)d_in[15];
    const float* W2  = (const float*)d_in[16];
    const float* b2  = (const float*)d_in[17];
    const float* W3  = (const float*)d_in[18];
    const float* b3  = (const float*)d_in[19];
    float* out = (float*)d_out;

    const int ip_smem = IP_SMEM_FLOATS * 4;   // 68352 B
    const int mb_smem = MB_SMEM_FLOATS * 4;   // 66976 B
    cudaFuncSetAttribute(k_inproj, cudaFuncAttributeMaxDynamicSharedMemorySize, ip_smem);
    cudaFuncSetAttribute(k_mamba,  cudaFuncAttributeMaxDynamicSharedMemorySize, mb_smem);

    k_embed<<<(TOKALL * DMODEL + 255) / 256, 256>>>(ids, emb);

    for (int layer = 0; layer < NLAYER; layer++) {
        // rmsnorm + in_proj: [TOK,64] @ [64,256] -> g_ures, per stack
        k_inproj<<<dim3(TOK / 128, 2, NSTACK), 256, ip_smem>>>(
            ip + (size_t)layer * DMODEL * 2 * DINNER,
            nw + (size_t)layer * DMODEL);

        // conv + x_proj + dt + scan + gate -> g_ys
        k_mamba<<<NSTACK * BATCH, 256, mb_smem>>>(xp, cw, cb, dw, db, al, dp, layer);

        // out_proj: [TOK,128] @ [128,64] -> residual add into g_x
        k_gemm<BUF_YS, BUF_X, 1><<<dim3(TOK / 64, 1, NSTACK), 256>>>(
            op + (size_t)layer * DINNER * DMODEL,
            DMODEL, DINNER, DINNER, DMODEL, DMODEL,
            (long long)TOK * DINNER, (long long)NLAYER * DINNER * DMODEL,
            (long long)TOK * DMODEL, 0);
    }

    k_fuse<<<(TOK * 32) / 256, 256>>>(nfw, fw);

    k_gemm<BUF_FUSED, BUF_H1P, 0><<<dim3(BATCH / 64, NH1 / 64, KSPLIT), 256>>>(
        W1, NH1, KCHUNK, FLAT, NH1, NH1,
        0, 0, (long long)BATCH * NH1, KCHUNK);

    k_brelu<<<(BATCH * NH1) / 256, 256>>>(b1);
    k_tail<<<2, 256>>>(W2, b2, W3, b3, out);
}